// round 11
// baseline (speedup 1.0000x reference)
#include <cuda_runtime.h>
#include <math.h>

#define F_IN   32
#define DDIM   128
#define HEADS  4
#define HD     512
#define RNN3   384
#define NSC    64
#define NBLK   (NSC + 2)         // bid0 = xr0 producer, bid1 = finale, 2.. = scanners
#define NTHR   512
#define LCAP   96
#define EB     4                 // edges per batch through one W_l pass

// Persistent globals (allocation-free rule). Finale resets all consumed state.
__device__ float g_num[HD];
__device__ float g_den[HEADS];
__device__ int   g_done;                 // incremented by the 65 non-finale blocks
__device__ volatile int g_xr0_flag;
__device__ float g_xr0[HD];

// ---- dynamic smem overlays (union: scanners/producer vs finale) ----
struct SMemScan {
    float part[EB * 4 * HD];   // 32 KB K-split partials
    float xle[EB * HD];        //  8 KB
    float hsb[EB * DDIM];      //  2 KB
    float nfb[EB * F_IN];
    float red[16];
    float psh[HEADS];
};
struct SMemFin {
    float Wih[RNN3 * DDIM];    // 192 KB — W_ih staged during the scan
    float gh[RNN3];            // hidden@W_hh.T + b_hh (b_ih stays on gi side)
    float hid[DDIM];
    float gat[DDIM];
    float gi[RNN3];
};
#define DYN_BYTES ((int)sizeof(SMemFin))

__global__ void __launch_bounds__(NTHR, 1) fused_stgat(
    const float* __restrict__ nf,     const float* __restrict__ hidden,
    const float* __restrict__ W_enc,  const float* __restrict__ b_enc,
    const float* __restrict__ W_l,    const float* __restrict__ b_l,
    const float* __restrict__ W_r,    const float* __restrict__ b_r,
    const float* __restrict__ att,    const float* __restrict__ gat_bias,
    const float* __restrict__ W_ih,   const float* __restrict__ W_hh,
    const float* __restrict__ b_ih,   const float* __restrict__ b_hh,
    const int*   __restrict__ ei,     int E,
    float* __restrict__ out)
{
    extern __shared__ __align__(16) char dynraw[];

    __shared__ int ls[LCAP];
    __shared__ int lcnt;

    const int t = threadIdx.x, b = blockIdx.x;
    const int warp = t >> 5, lane = t & 31;
    const int grp = t >> 7, q = t & 127;
    const int n4 = E >> 2;

    if (b == 0) {
        // ======== Producer: xr0 = (relu(nf0@W_enc+b_enc)) @ W_r + b_r ========
        SMemScan& s = *reinterpret_cast<SMemScan*>(dynraw);
        if (t < F_IN) s.nfb[t] = nf[t];
        __syncthreads();
        {
            float a = 0.f;
            #pragma unroll
            for (int k = 0; k < 8; k++)
                a += s.nfb[grp*8 + k] * W_enc[(grp*8 + k)*DDIM + q];
            s.part[grp*DDIM + q] = a;
        }
        __syncthreads();
        if (t < DDIM)
            s.hsb[t] = fmaxf(b_enc[t] + s.part[t] + s.part[DDIM+t] + s.part[2*DDIM+t] + s.part[3*DDIM+t], 0.f);
        __syncthreads();
        {
            float4 a = make_float4(0.f, 0.f, 0.f, 0.f);
            const float* Wb = W_r + (size_t)(grp*32)*HD + 4*q;
            #pragma unroll
            for (int j = 0; j < 32; j++) {
                const float4 wv = *(const float4*)(Wb + (size_t)j*HD);
                const float hv = s.hsb[grp*32 + j];
                a.x += hv*wv.x; a.y += hv*wv.y; a.z += hv*wv.z; a.w += hv*wv.w;
            }
            *(float4*)(s.part + grp*HD + 4*q) = a;
        }
        __syncthreads();
        g_xr0[t] = b_r[t] + s.part[t] + s.part[HD+t] + s.part[2*HD+t] + s.part[3*HD+t];
        __threadfence();
        __syncthreads();
        if (t == 0) { g_xr0_flag = 1; atomicAdd(&g_done, 1); }
        return;
    }

    if (b == 1) {
        // ======== Dedicated finale: preload W_ih to SMEM + gh, then wait ========
        SMemFin& f = *reinterpret_cast<SMemFin*>(dynraw);

        if (t < DDIM) f.hid[t] = hidden[t];
        __syncthreads();

        // gh = hidden @ W_hh.T + b_hh  (16 warps x 24 rows, float4, global W_hh)
        {
            const int base = warp * 24;
            const float x0 = f.hid[lane*4+0], x1 = f.hid[lane*4+1];
            const float x2 = f.hid[lane*4+2], x3 = f.hid[lane*4+3];
            for (int i = 0; i < 24; i += 4) {
                float acc[4];
                #pragma unroll
                for (int j = 0; j < 4; j++) {
                    const float4 wv = *(const float4*)(W_hh + (size_t)(base+i+j)*DDIM + lane*4);
                    acc[j] = wv.x*x0 + wv.y*x1 + wv.z*x2 + wv.w*x3;
                }
                #pragma unroll
                for (int off = 16; off; off >>= 1)
                    #pragma unroll
                    for (int j = 0; j < 4; j++)
                        acc[j] += __shfl_xor_sync(0xffffffffu, acc[j], off);
                if (lane == 0)
                    #pragma unroll
                    for (int j = 0; j < 4; j++)
                        f.gh[base+i+j] = acc[j] + b_hh[base+i+j];
            }
        }

        // Stage all of W_ih into SMEM (192 KB) — overlapped with the scan.
        {
            const float4* src = (const float4*)W_ih;
            float4* dst = (float4*)f.Wih;
            #pragma unroll
            for (int i = 0; i < RNN3*DDIM/4/NTHR; i++)   // 24 iters
                dst[i*NTHR + t] = src[i*NTHR + t];
        }
        __syncthreads();

        // Wait for producer + all scanners (65 arrivals)
        if (t == 0) {
            volatile int* dn = &g_done;
            while (*dn < NBLK - 1) { __nanosleep(64); }
        }
        __syncthreads();
        __threadfence();    // acquire scanners' atomics

        if (t < DDIM) {
            float s = 0.f;
            #pragma unroll
            for (int h = 0; h < HEADS; h++)
                s += g_num[h*DDIM + t] / fmaxf(g_den[h], 1e-16f);
            f.gat[t] = 0.25f * s + gat_bias[t];
        }
        __syncthreads();

        // reset persistent state for the next graph replay
        g_num[t] = 0.f;
        if (t < HEADS) g_den[t] = 0.f;
        if (t == 0) { g_done = 0; g_xr0_flag = 0; }

        // gi = gat @ W_ih.T + b_ih — W_ih now SMEM-resident
        {
            const int base = warp * 24;
            const float x0 = f.gat[lane*4+0], x1 = f.gat[lane*4+1];
            const float x2 = f.gat[lane*4+2], x3 = f.gat[lane*4+3];
            for (int i = 0; i < 24; i += 4) {
                float acc[4];
                #pragma unroll
                for (int j = 0; j < 4; j++) {
                    const float4 wv = *(const float4*)(f.Wih + (base+i+j)*DDIM + lane*4);
                    acc[j] = wv.x*x0 + wv.y*x1 + wv.z*x2 + wv.w*x3;
                }
                #pragma unroll
                for (int off = 16; off; off >>= 1)
                    #pragma unroll
                    for (int j = 0; j < 4; j++)
                        acc[j] += __shfl_xor_sync(0xffffffffu, acc[j], off);
                if (lane == 0)
                    #pragma unroll
                    for (int j = 0; j < 4; j++)
                        f.gi[base+i+j] = acc[j] + b_ih[base+i+j];   // b_ih on gi side
            }
        }
        __syncthreads();

        if (t < DDIM) {
            const float r  = 1.f / (1.f + expf(-(f.gi[t]        + f.gh[t])));
            const float z  = 1.f / (1.f + expf(-(f.gi[DDIM+t]   + f.gh[DDIM+t])));
            const float ng = tanhf(f.gi[2*DDIM+t] + r * f.gh[2*DDIM+t]);
            out[t] = (1.f - z) * ng + z * f.hid[t];
        }
        return;
    }

    // ================= Scanner blocks (bids 2..65) =================
    SMemScan& s = *reinterpret_cast<SMemScan*>(dynraw);
    if (t == 0) lcnt = 0;
    __syncthreads();

    const int idx = b - 2;
    const int chunk = (n4 + NSC - 1) / NSC;
    const int lo = idx * chunk;
    const int hi = min(n4, lo + chunk);
    const int4* dst4 = (const int4*)(ei + E);
    if (idx == 0) {
        if (t == 0) ls[atomicAdd(&lcnt, 1)] = 0;    // self-loop of node 0
        for (int i = 4*n4 + t; i < E; i += NTHR)    // tail if E % 4
            if (ei[E + i] == 0) ls[atomicAdd(&lcnt, 1)] = ei[i];
    }
    for (int i = lo + t; i < hi; i += NTHR) {
        int4 v = dst4[i];
        if (v.x == 0) ls[atomicAdd(&lcnt, 1)] = ei[4*i+0];
        if (v.y == 0) ls[atomicAdd(&lcnt, 1)] = ei[4*i+1];
        if (v.z == 0) ls[atomicAdd(&lcnt, 1)] = ei[4*i+2];
        if (v.w == 0) ls[atomicAdd(&lcnt, 1)] = ei[4*i+3];
    }
    __syncthreads();

    const int cnt = min(lcnt, LCAP);
    if (cnt > 0) {
        bool got = false;
        float myxr0 = 0.f;
        float accN = 0.f;
        float accD = 0.f;
        const float attv = att[t];   // att [4,128] row-major == att[t]
        const float blv  = b_l[t];

        for (int base = 0; base < cnt; base += EB) {
            const int nb = min(EB, cnt - base);

            if (t < nb * F_IN) {   // stage nf rows
                const int e = t >> 5, k = t & 31;
                s.nfb[e*F_IN + k] = nf[(size_t)ls[base + e]*F_IN + k];
            }
            __syncthreads();
            if (grp < nb) {        // hs for up to 4 edges in parallel
                float a = b_enc[q];
                #pragma unroll
                for (int k = 0; k < F_IN; k++)
                    a += s.nfb[grp*F_IN + k] * W_enc[k*DDIM + q];
                s.hsb[grp*DDIM + q] = fmaxf(a, 0.f);
            }
            __syncthreads();
            {   // xl for all batch edges through ONE W_l pass (float4 K-split)
                float4 a0 = make_float4(0.f,0.f,0.f,0.f);
                float4 a1 = a0, a2 = a0, a3 = a0;
                const float* Wb = W_l + (size_t)(grp*32)*HD + 4*q;
                #pragma unroll
                for (int j = 0; j < 32; j++) {
                    const float4 wv = *(const float4*)(Wb + (size_t)j*HD);
                    const int d = grp*32 + j;
                    float hv;
                    hv = s.hsb[0*DDIM + d];
                    a0.x += hv*wv.x; a0.y += hv*wv.y; a0.z += hv*wv.z; a0.w += hv*wv.w;
                    if (nb > 1) { hv = s.hsb[1*DDIM + d];
                        a1.x += hv*wv.x; a1.y += hv*wv.y; a1.z += hv*wv.z; a1.w += hv*wv.w; }
                    if (nb > 2) { hv = s.hsb[2*DDIM + d];
                        a2.x += hv*wv.x; a2.y += hv*wv.y; a2.z += hv*wv.z; a2.w += hv*wv.w; }
                    if (nb > 3) { hv = s.hsb[3*DDIM + d];
                        a3.x += hv*wv.x; a3.y += hv*wv.y; a3.z += hv*wv.z; a3.w += hv*wv.w; }
                }
                *(float4*)(s.part + 0*4*HD + grp*HD + 4*q) = a0;
                if (nb > 1) *(float4*)(s.part + 1*4*HD + grp*HD + 4*q) = a1;
                if (nb > 2) *(float4*)(s.part + 2*4*HD + grp*HD + 4*q) = a2;
                if (nb > 3) *(float4*)(s.part + 3*4*HD + grp*HD + 4*q) = a3;
            }
            __syncthreads();
            for (int e = 0; e < nb; e++) {
                const float* pe = s.part + e*4*HD;
                s.xle[e*HD + t] = blv + pe[t] + pe[HD+t] + pe[2*HD+t] + pe[3*HD+t];
            }

            if (!got) {   // xr0 needed only from the leaky step onward
                if (t == 0) { while (g_xr0_flag == 0) { __nanosleep(32); } }
                __syncthreads();
                __threadfence();
                myxr0 = g_xr0[t];
                got = true;
            }
            __syncthreads();

            for (int e = 0; e < nb; e++) {
                const float xlv = s.xle[e*HD + t];
                const float xs = xlv + myxr0;
                const float lr = xs >= 0.f ? xs : 0.2f * xs;   // leaky 0.2
                float v = lr * attv;
                #pragma unroll
                for (int off = 16; off; off >>= 1)
                    v += __shfl_xor_sync(0xffffffffu, v, off);
                if (lane == 0) s.red[warp] = v;
                __syncthreads();
                if (t < HEADS) {
                    // softmax shift dropped (shift-invariant; logits O(1))
                    float p = __expf(s.red[4*t] + s.red[4*t+1] + s.red[4*t+2] + s.red[4*t+3]);
                    s.psh[t] = p;
                    accD += p;
                }
                __syncthreads();
                accN += s.psh[t >> 7] * xlv;
                __syncthreads();
            }
        }
        atomicAdd(&g_num[t], accN);
        if (t < HEADS) atomicAdd(&g_den[t], accD);
    }

    __threadfence();
    __syncthreads();
    if (t == 0) atomicAdd(&g_done, 1);
}

extern "C" void kernel_launch(void* const* d_in, const int* in_sizes, int n_in,
                              void* d_out, int out_size) {
    const float* nf       = (const float*)d_in[0];
    const float* hidden   = (const float*)d_in[1];
    const float* W_enc    = (const float*)d_in[2];
    const float* b_enc    = (const float*)d_in[3];
    const float* W_l      = (const float*)d_in[4];
    const float* b_l      = (const float*)d_in[5];
    const float* W_r      = (const float*)d_in[6];
    const float* b_r      = (const float*)d_in[7];
    const float* att      = (const float*)d_in[8];
    const float* gat_bias = (const float*)d_in[9];
    const float* W_ih     = (const float*)d_in[10];
    const float* W_hh     = (const float*)d_in[11];
    const float* b_ih     = (const float*)d_in[12];
    const float* b_hh     = (const float*)d_in[13];
    const int*   ei       = (const int*)d_in[14];
    float* out = (float*)d_out;

    int E = in_sizes[14] / 2;

    static int attr_set = 0;
    if (!attr_set) {
        cudaFuncSetAttribute(fused_stgat, cudaFuncAttributeMaxDynamicSharedMemorySize,
                             DYN_BYTES);
        attr_set = 1;
    }
    fused_stgat<<<NBLK, NTHR, DYN_BYTES>>>(
        nf, hidden, W_enc, b_enc, W_l, b_l, W_r, b_r,
        att, gat_bias, W_ih, W_hh, b_ih, b_hh, ei, E, out);
}

// round 12
// speedup vs baseline: 1.0171x; 1.0171x over previous
#include <cuda_runtime.h>
#include <math.h>

#define F_IN   32
#define DDIM   128
#define HEADS  4
#define HD     512
#define RNN3   384
#define NPROD  4                  // bids 0..3: xr0 quarter producers
#define FINB   4                  // bid 4: finale
#define NSC    96                 // bids 5..100: scanners
#define NBLK   (NPROD + 1 + NSC)  // 101
#define NTHR   512
#define LCAP   96
#define EB     4                  // edges per batch through one W_l pass

// Persistent globals (allocation-free rule). Finale resets all consumed state.
__device__ float g_num[HD];
__device__ float g_den[HEADS];
__device__ int   g_done;          // incremented by scanners only
__device__ int   g_xr0_done;      // incremented by the 4 producers
__device__ float g_xr0[HD];

struct SMemScan {
    float part[EB * 4 * HD];   // 32 KB K-split partials
    float xle[EB * HD];        //  8 KB
    float hsb[EB * DDIM];
    float nfb[EB * F_IN];
    float red[16];
    float psh[HEADS];
};
struct SMemFin {
    float Wih[RNN3 * DDIM];    // 192 KB, staged during the scan
    float gh[RNN3];            // hidden@W_hh.T + b_hh (b_ih stays on gi side)
    float hid[DDIM];
    float gat[DDIM];
    float gi[RNN3];
};
#define DYN_BYTES ((int)sizeof(SMemFin))

__global__ void __launch_bounds__(NTHR, 1) fused_stgat(
    const float* __restrict__ nf,     const float* __restrict__ hidden,
    const float* __restrict__ W_enc,  const float* __restrict__ b_enc,
    const float* __restrict__ W_l,    const float* __restrict__ b_l,
    const float* __restrict__ W_r,    const float* __restrict__ b_r,
    const float* __restrict__ att,    const float* __restrict__ gat_bias,
    const float* __restrict__ W_ih,   const float* __restrict__ W_hh,
    const float* __restrict__ b_ih,   const float* __restrict__ b_hh,
    const int*   __restrict__ ei,     int E,
    float* __restrict__ out)
{
    extern __shared__ __align__(16) char dynraw[];

    __shared__ int ls[LCAP];
    __shared__ int lcnt;

    const int t = threadIdx.x, b = blockIdx.x;
    const int warp = t >> 5, lane = t & 31;
    const int grp = t >> 7, q = t & 127;
    const int n4 = E >> 2;

    if (b < NPROD) {
        // ======== xr0 quarter producer: dims [128b, 128b+128) ========
        SMemScan& s = *reinterpret_cast<SMemScan*>(dynraw);
        if (t < F_IN) s.nfb[t] = nf[t];
        __syncthreads();
        {   // h0 partials (4-way K split over W_enc)
            float a = 0.f;
            #pragma unroll
            for (int k = 0; k < 8; k++)
                a += s.nfb[grp*8 + k] * W_enc[(grp*8 + k)*DDIM + q];
            s.part[grp*DDIM + q] = a;
        }
        __syncthreads();
        if (t < DDIM)
            s.hsb[t] = fmaxf(b_enc[t] + s.part[t] + s.part[DDIM+t] + s.part[2*DDIM+t] + s.part[3*DDIM+t], 0.f);
        __syncthreads();
        {   // quarter matvec: thread (grp=kslice, q): 32 coalesced W_r loads
            float a = 0.f;
            const float* Wb = W_r + (size_t)(grp*32)*HD + b*DDIM + q;
            #pragma unroll
            for (int j = 0; j < 32; j++)
                a += s.hsb[grp*32 + j] * Wb[(size_t)j*HD];
            s.part[grp*DDIM + q] = a;
        }
        __syncthreads();
        if (t < DDIM)
            g_xr0[b*DDIM + t] = b_r[b*DDIM + t]
                + s.part[t] + s.part[DDIM+t] + s.part[2*DDIM+t] + s.part[3*DDIM+t];
        __threadfence();
        __syncthreads();
        if (t == 0) atomicAdd(&g_xr0_done, 1);
        return;
    }

    if (b == FINB) {
        // ======== Dedicated finale: preload W_ih smem + gh, then wait ========
        SMemFin& f = *reinterpret_cast<SMemFin*>(dynraw);

        if (t < DDIM) f.hid[t] = hidden[t];
        __syncthreads();
        {   // gh = hidden @ W_hh.T + b_hh (16 warps x 24 rows, float4)
            const int base = warp * 24;
            const float x0 = f.hid[lane*4+0], x1 = f.hid[lane*4+1];
            const float x2 = f.hid[lane*4+2], x3 = f.hid[lane*4+3];
            for (int i = 0; i < 24; i += 4) {
                float acc[4];
                #pragma unroll
                for (int j = 0; j < 4; j++) {
                    const float4 wv = *(const float4*)(W_hh + (size_t)(base+i+j)*DDIM + lane*4);
                    acc[j] = wv.x*x0 + wv.y*x1 + wv.z*x2 + wv.w*x3;
                }
                #pragma unroll
                for (int off = 16; off; off >>= 1)
                    #pragma unroll
                    for (int j = 0; j < 4; j++)
                        acc[j] += __shfl_xor_sync(0xffffffffu, acc[j], off);
                if (lane == 0)
                    #pragma unroll
                    for (int j = 0; j < 4; j++)
                        f.gh[base+i+j] = acc[j] + b_hh[base+i+j];
            }
        }
        {   // stage W_ih (192 KB) — overlapped with the scan
            const float4* src = (const float4*)W_ih;
            float4* dst = (float4*)f.Wih;
            #pragma unroll
            for (int i = 0; i < RNN3*DDIM/4/NTHR; i++)
                dst[i*NTHR + t] = src[i*NTHR + t];
        }
        __syncthreads();

        if (t == 0) {   // wait for all scanners
            volatile int* dn = &g_done;
            while (*dn < NSC) { __nanosleep(64); }
        }
        __syncthreads();
        __threadfence();

        if (t < DDIM) {
            float s = 0.f;
            #pragma unroll
            for (int h = 0; h < HEADS; h++)
                s += g_num[h*DDIM + t] / fmaxf(g_den[h], 1e-16f);
            f.gat[t] = 0.25f * s + gat_bias[t];
        }
        __syncthreads();

        // reset persistent state for the next graph replay
        g_num[t] = 0.f;
        if (t < HEADS) g_den[t] = 0.f;
        if (t == 0) { g_done = 0; g_xr0_done = 0; }

        {   // gi = gat @ W_ih.T + b_ih (W_ih smem-resident)
            const int base = warp * 24;
            const float x0 = f.gat[lane*4+0], x1 = f.gat[lane*4+1];
            const float x2 = f.gat[lane*4+2], x3 = f.gat[lane*4+3];
            for (int i = 0; i < 24; i += 4) {
                float acc[4];
                #pragma unroll
                for (int j = 0; j < 4; j++) {
                    const float4 wv = *(const float4*)(f.Wih + (base+i+j)*DDIM + lane*4);
                    acc[j] = wv.x*x0 + wv.y*x1 + wv.z*x2 + wv.w*x3;
                }
                #pragma unroll
                for (int off = 16; off; off >>= 1)
                    #pragma unroll
                    for (int j = 0; j < 4; j++)
                        acc[j] += __shfl_xor_sync(0xffffffffu, acc[j], off);
                if (lane == 0)
                    #pragma unroll
                    for (int j = 0; j < 4; j++)
                        f.gi[base+i+j] = acc[j] + b_ih[base+i+j];  // b_ih on gi side
            }
        }
        __syncthreads();

        if (t < DDIM) {
            const float r  = 1.f / (1.f + expf(-(f.gi[t]        + f.gh[t])));
            const float z  = 1.f / (1.f + expf(-(f.gi[DDIM+t]   + f.gh[DDIM+t])));
            const float ng = tanhf(f.gi[2*DDIM+t] + r * f.gh[2*DDIM+t]);
            out[t] = (1.f - z) * ng + z * f.hid[t];
        }
        return;
    }

    // ================= Scanner blocks (bids 5..100) =================
    SMemScan& s = *reinterpret_cast<SMemScan*>(dynraw);
    if (t == 0) lcnt = 0;
    __syncthreads();

    const int idx = b - NPROD - 1;
    const int chunk = (n4 + NSC - 1) / NSC;
    const int lo = idx * chunk;
    const int hi = min(n4, lo + chunk);
    const int4* dst4 = (const int4*)(ei + E);
    if (idx == 0) {
        if (t == 0) ls[atomicAdd(&lcnt, 1)] = 0;    // self-loop of node 0
        for (int i = 4*n4 + t; i < E; i += NTHR)    // tail if E % 4
            if (ei[E + i] == 0) ls[atomicAdd(&lcnt, 1)] = ei[i];
    }
    for (int i = lo + t; i < hi; i += NTHR) {
        int4 v = dst4[i];
        if (v.x == 0) ls[atomicAdd(&lcnt, 1)] = ei[4*i+0];
        if (v.y == 0) ls[atomicAdd(&lcnt, 1)] = ei[4*i+1];
        if (v.z == 0) ls[atomicAdd(&lcnt, 1)] = ei[4*i+2];
        if (v.w == 0) ls[atomicAdd(&lcnt, 1)] = ei[4*i+3];
    }
    __syncthreads();

    const int cnt = min(lcnt, LCAP);
    if (cnt > 0) {
        bool got = false;
        float myxr0 = 0.f;
        float accN = 0.f;
        float accD = 0.f;
        const float attv = att[t];   // att [4,128] row-major == att[t]
        const float blv  = b_l[t];

        for (int base = 0; base < cnt; base += EB) {
            const int nb = min(EB, cnt - base);

            if (t < nb * F_IN) {   // stage nf rows
                const int e = t >> 5, k = t & 31;
                s.nfb[e*F_IN + k] = nf[(size_t)ls[base + e]*F_IN + k];
            }
            __syncthreads();
            if (grp < nb) {        // hs for up to 4 edges in parallel
                float a = b_enc[q];
                #pragma unroll
                for (int k = 0; k < F_IN; k++)
                    a += s.nfb[grp*F_IN + k] * W_enc[k*DDIM + q];
                s.hsb[grp*DDIM + q] = fmaxf(a, 0.f);
            }
            __syncthreads();
            {   // xl for all batch edges through ONE W_l pass (float4 K-split)
                float4 a0 = make_float4(0.f,0.f,0.f,0.f);
                float4 a1 = a0, a2 = a0, a3 = a0;
                const float* Wb = W_l + (size_t)(grp*32)*HD + 4*q;
                #pragma unroll
                for (int j = 0; j < 32; j++) {
                    const float4 wv = *(const float4*)(Wb + (size_t)j*HD);
                    const int d = grp*32 + j;
                    float hv;
                    hv = s.hsb[0*DDIM + d];
                    a0.x += hv*wv.x; a0.y += hv*wv.y; a0.z += hv*wv.z; a0.w += hv*wv.w;
                    if (nb > 1) { hv = s.hsb[1*DDIM + d];
                        a1.x += hv*wv.x; a1.y += hv*wv.y; a1.z += hv*wv.z; a1.w += hv*wv.w; }
                    if (nb > 2) { hv = s.hsb[2*DDIM + d];
                        a2.x += hv*wv.x; a2.y += hv*wv.y; a2.z += hv*wv.z; a2.w += hv*wv.w; }
                    if (nb > 3) { hv = s.hsb[3*DDIM + d];
                        a3.x += hv*wv.x; a3.y += hv*wv.y; a3.z += hv*wv.z; a3.w += hv*wv.w; }
                }
                *(float4*)(s.part + 0*4*HD + grp*HD + 4*q) = a0;
                if (nb > 1) *(float4*)(s.part + 1*4*HD + grp*HD + 4*q) = a1;
                if (nb > 2) *(float4*)(s.part + 2*4*HD + grp*HD + 4*q) = a2;
                if (nb > 3) *(float4*)(s.part + 3*4*HD + grp*HD + 4*q) = a3;
            }
            __syncthreads();
            for (int e = 0; e < nb; e++) {
                const float* pe = s.part + e*4*HD;
                s.xle[e*HD + t] = blv + pe[t] + pe[HD+t] + pe[2*HD+t] + pe[3*HD+t];
            }

            if (!got) {   // xr0 needed only from the leaky step onward
                if (t == 0) {
                    volatile int* xd = &g_xr0_done;
                    while (*xd < NPROD) {}
                }
                __syncthreads();
                __threadfence();
                myxr0 = g_xr0[t];
                got = true;
            }
            __syncthreads();

            for (int e = 0; e < nb; e++) {
                const float xlv = s.xle[e*HD + t];
                const float xs = xlv + myxr0;
                const float lr = xs >= 0.f ? xs : 0.2f * xs;   // leaky 0.2
                float v = lr * attv;
                #pragma unroll
                for (int off = 16; off; off >>= 1)
                    v += __shfl_xor_sync(0xffffffffu, v, off);
                if (lane == 0) s.red[warp] = v;
                __syncthreads();
                if (t < HEADS) {
                    // softmax shift dropped (shift-invariant; logits O(1))
                    float p = __expf(s.red[4*t] + s.red[4*t+1] + s.red[4*t+2] + s.red[4*t+3]);
                    s.psh[t] = p;
                    accD += p;
                }
                __syncthreads();
                accN += s.psh[t >> 7] * xlv;
                __syncthreads();
            }
        }
        atomicAdd(&g_num[t], accN);
        if (t < HEADS) atomicAdd(&g_den[t], accD);
    }

    __threadfence();
    __syncthreads();
    if (t == 0) atomicAdd(&g_done, 1);
}

extern "C" void kernel_launch(void* const* d_in, const int* in_sizes, int n_in,
                              void* d_out, int out_size) {
    const float* nf       = (const float*)d_in[0];
    const float* hidden   = (const float*)d_in[1];
    const float* W_enc    = (const float*)d_in[2];
    const float* b_enc    = (const float*)d_in[3];
    const float* W_l      = (const float*)d_in[4];
    const float* b_l      = (const float*)d_in[5];
    const float* W_r      = (const float*)d_in[6];
    const float* b_r      = (const float*)d_in[7];
    const float* att      = (const float*)d_in[8];
    const float* gat_bias = (const float*)d_in[9];
    const float* W_ih     = (const float*)d_in[10];
    const float* W_hh     = (const float*)d_in[11];
    const float* b_ih     = (const float*)d_in[12];
    const float* b_hh     = (const float*)d_in[13];
    const int*   ei       = (const int*)d_in[14];
    float* out = (float*)d_out;

    int E = in_sizes[14] / 2;

    static int attr_set = 0;
    if (!attr_set) {
        cudaFuncSetAttribute(fused_stgat, cudaFuncAttributeMaxDynamicSharedMemorySize,
                             DYN_BYTES);
        attr_set = 1;
    }
    fused_stgat<<<NBLK, NTHR, DYN_BYTES>>>(
        nf, hidden, W_enc, b_enc, W_l, b_l, W_r, b_r,
        att, gat_bias, W_ih, W_hh, b_ih, b_hh, ei, E, out);
}

// round 13
// speedup vs baseline: 1.0347x; 1.0174x over previous
#include <cuda_runtime.h>
#include <math.h>

#define F_IN   32
#define DDIM   128
#define HEADS  4
#define HD     512
#define RNN3   384
#define NPROD  4                   // bids 0..3: xr0 quarter producers
#define NFIN   8                   // bids 4..11: GRU slice finales
#define NSC    48                  // bids 12..59: scanners
#define NBLK   (NPROD + NFIN + NSC)
#define NTHR   512
#define LCAP   96
#define EB     4                   // edges per batch through one W_l pass

// Persistent globals (allocation-free rule). Last slice finale resets state.
__device__ float g_num[HD];
__device__ float g_den[HEADS];
__device__ int   g_done;           // scanners
__device__ int   g_xr0_done;       // producers
__device__ int   g_fin;            // slice finales
__device__ float g_xr0[HD];

struct SMemScan {
    float part[EB * 4 * HD];   // 32 KB K-split partials
    float xle[EB * HD];        //  8 KB
    float hsb[EB * DDIM];
    float nfb[EB * F_IN];
    float red[16];
    float psh[HEADS];
};
struct SMemFin {
    float Wih[48 * DDIM];      // 24 KB: my 48 W_ih rows, staged during scan
    float hid[DDIM];
    float gat[DDIM];
    float ghpart[384];
    float ghs[48];             // gh + b_hh (layout g*16+k)
    float bihs[48];            // b_ih kept separate (n-gate: i_n + r*h_n)
    float gis[48];
    int   reset_me;
};
#define DYN_BYTES 45056

__global__ void __launch_bounds__(NTHR, 1) fused_stgat(
    const float* __restrict__ nf,     const float* __restrict__ hidden,
    const float* __restrict__ W_enc,  const float* __restrict__ b_enc,
    const float* __restrict__ W_l,    const float* __restrict__ b_l,
    const float* __restrict__ W_r,    const float* __restrict__ b_r,
    const float* __restrict__ att,    const float* __restrict__ gat_bias,
    const float* __restrict__ W_ih,   const float* __restrict__ W_hh,
    const float* __restrict__ b_ih,   const float* __restrict__ b_hh,
    const int*   __restrict__ ei,     int E,
    float* __restrict__ out)
{
    extern __shared__ __align__(16) char dynraw[];
    __shared__ int ls[LCAP];
    __shared__ int lcnt;

    const int t = threadIdx.x, b = blockIdx.x;
    const int warp = t >> 5, lane = t & 31;
    const int grp = t >> 7, q = t & 127;
    const int n4 = E >> 2;

    if (b < NPROD) {
        // ======== xr0 quarter producer: dims [128b, 128b+128) ========
        SMemScan& s = *reinterpret_cast<SMemScan*>(dynraw);
        if (t < F_IN) s.nfb[t] = nf[t];
        __syncthreads();
        {
            float a = 0.f;
            #pragma unroll
            for (int k = 0; k < 8; k++)
                a += s.nfb[grp*8 + k] * W_enc[(grp*8 + k)*DDIM + q];
            s.part[grp*DDIM + q] = a;
        }
        __syncthreads();
        if (t < DDIM)
            s.hsb[t] = fmaxf(b_enc[t] + s.part[t] + s.part[DDIM+t] + s.part[2*DDIM+t] + s.part[3*DDIM+t], 0.f);
        __syncthreads();
        {
            float a = 0.f;
            const float* Wb = W_r + (size_t)(grp*32)*HD + b*DDIM + q;
            #pragma unroll
            for (int j = 0; j < 32; j++)
                a += s.hsb[grp*32 + j] * Wb[(size_t)j*HD];
            s.part[grp*DDIM + q] = a;
        }
        __syncthreads();
        if (t < DDIM)
            g_xr0[b*DDIM + t] = b_r[b*DDIM + t]
                + s.part[t] + s.part[DDIM+t] + s.part[2*DDIM+t] + s.part[3*DDIM+t];
        __threadfence();
        __syncthreads();
        if (t == 0) atomicAdd(&g_xr0_done, 1);
        return;
    }

    if (b < NPROD + NFIN) {
        // ======== Slice finale w: GRU rows {128g+16w+k}, out dims [16w,16w+16) ========
        const int w = b - NPROD;
        SMemFin& f = *reinterpret_cast<SMemFin*>(dynraw);

        if (t < DDIM) f.hid[t] = hidden[t];
        __syncthreads();

        // gh slice = hidden @ W_hh rows  (proven R8/R9 mapping)
        if (t < 384) {
            const int g = t / 128, rem = t % 128, k = rem >> 3, kg = rem & 7;
            const int R = 128*g + 16*w + k;
            const float* Wr = W_hh + (size_t)R * DDIM;
            float a = 0.f;
            #pragma unroll
            for (int c = kg*16; c < kg*16 + 16; c++) a += f.hid[c] * Wr[c];
            f.ghpart[t] = a;
        }
        // stage my 48 W_ih rows -> smem (1536 float4; 3 per thread)
        for (int i = t; i < 48*DDIM/4; i += NTHR) {
            const int row = i >> 5, f4 = i & 31;        // 32 float4 per row
            const int g = row >> 4, k = row & 15;
            ((float4*)f.Wih)[i] =
                ((const float4*)W_ih)[(size_t)(128*g + 16*w + k)*32 + f4];
        }
        __syncthreads();
        if (t < 48) {
            const int g = t / 16, k = t % 16;
            const int R = 128*g + 16*w + k;
            float a = b_hh[R];
            #pragma unroll
            for (int kg = 0; kg < 8; kg++) a += f.ghpart[g*128 + k*8 + kg];
            f.ghs[t] = a;
            f.bihs[t] = b_ih[R];
        }

        // ---- single rendezvous: wait for all scanners ----
        if (t == 0) {
            volatile int* dn = &g_done;
            while (*dn < NSC) { __nanosleep(32); }
        }
        __syncthreads();
        __threadfence();

        if (t < DDIM) {
            float s = 0.f;
            #pragma unroll
            for (int h = 0; h < HEADS; h++)
                s += g_num[h*DDIM + t] / fmaxf(g_den[h], 1e-16f);
            f.gat[t] = 0.25f * s + gat_bias[t];
        }
        __syncthreads();

        // gi: warp per row (lane = one float4 of the row), 3 rows per warp
        {
            const float4 gv = ((const float4*)f.gat)[lane];
            #pragma unroll
            for (int rr = 0; rr < 3; rr++) {
                const int row = warp*3 + rr;
                const float4 wv = ((const float4*)f.Wih)[row*32 + lane];
                float a = wv.x*gv.x + wv.y*gv.y + wv.z*gv.z + wv.w*gv.w;
                #pragma unroll
                for (int off = 16; off; off >>= 1)
                    a += __shfl_xor_sync(0xffffffffu, a, off);
                if (lane == 0) f.gis[row] = a + f.bihs[row];
            }
        }
        __syncthreads();

        if (t < 16) {
            const float r  = 1.f / (1.f + expf(-(f.gis[t]      + f.ghs[t])));
            const float z  = 1.f / (1.f + expf(-(f.gis[16 + t] + f.ghs[16 + t])));
            const float ng = tanhf(f.gis[32 + t] + r * f.ghs[32 + t]);
            out[16*w + t] = (1.f - z) * ng + z * f.hid[16*w + t];
        }
        __threadfence();
        __syncthreads();

        // last-arriving finale resets persistent state for the next replay
        if (t == 0) f.reset_me = (atomicAdd(&g_fin, 1) == NFIN - 1);
        __syncthreads();
        if (f.reset_me) {
            g_num[t] = 0.f;
            if (t < HEADS) g_den[t] = 0.f;
            if (t == 0) { g_done = 0; g_xr0_done = 0; g_fin = 0; }
        }
        return;
    }

    // ================= Scanner blocks (bids 12..59) =================
    SMemScan& s = *reinterpret_cast<SMemScan*>(dynraw);
    if (t == 0) lcnt = 0;
    __syncthreads();

    const int idx = b - NPROD - NFIN;
    const int chunk = (n4 + NSC - 1) / NSC;
    const int lo = idx * chunk;
    const int hi = min(n4, lo + chunk);
    const int4* dst4 = (const int4*)(ei + E);
    if (idx == 0) {
        if (t == 0) ls[atomicAdd(&lcnt, 1)] = 0;    // self-loop of node 0
        for (int i = 4*n4 + t; i < E; i += NTHR)    // tail if E % 4
            if (ei[E + i] == 0) ls[atomicAdd(&lcnt, 1)] = ei[i];
    }
    for (int i = lo + t; i < hi; i += NTHR) {
        int4 v = dst4[i];
        if (v.x == 0) ls[atomicAdd(&lcnt, 1)] = ei[4*i+0];
        if (v.y == 0) ls[atomicAdd(&lcnt, 1)] = ei[4*i+1];
        if (v.z == 0) ls[atomicAdd(&lcnt, 1)] = ei[4*i+2];
        if (v.w == 0) ls[atomicAdd(&lcnt, 1)] = ei[4*i+3];
    }
    __syncthreads();

    const int cnt = min(lcnt, LCAP);
    if (cnt > 0) {
        bool got = false;
        float myxr0 = 0.f;
        float accN = 0.f;
        float accD = 0.f;
        const float attv = att[t];   // att [4,128] row-major == att[t]
        const float blv  = b_l[t];

        for (int base = 0; base < cnt; base += EB) {
            const int nb = min(EB, cnt - base);

            if (t < nb * F_IN) {   // stage nf rows
                const int e = t >> 5, k = t & 31;
                s.nfb[e*F_IN + k] = nf[(size_t)ls[base + e]*F_IN + k];
            }
            __syncthreads();
            if (grp < nb) {        // hs for up to 4 edges in parallel
                float a = b_enc[q];
                #pragma unroll
                for (int k = 0; k < F_IN; k++)
                    a += s.nfb[grp*F_IN + k] * W_enc[k*DDIM + q];
                s.hsb[grp*DDIM + q] = fmaxf(a, 0.f);
            }
            __syncthreads();
            {   // xl for all batch edges through ONE W_l pass (float4 K-split)
                float4 a0 = make_float4(0.f,0.f,0.f,0.f);
                float4 a1 = a0, a2 = a0, a3 = a0;
                const float* Wb = W_l + (size_t)(grp*32)*HD + 4*q;
                #pragma unroll
                for (int j = 0; j < 32; j++) {
                    const float4 wv = *(const float4*)(Wb + (size_t)j*HD);
                    const int d = grp*32 + j;
                    float hv;
                    hv = s.hsb[0*DDIM + d];
                    a0.x += hv*wv.x; a0.y += hv*wv.y; a0.z += hv*wv.z; a0.w += hv*wv.w;
                    if (nb > 1) { hv = s.hsb[1*DDIM + d];
                        a1.x += hv*wv.x; a1.y += hv*wv.y; a1.z += hv*wv.z; a1.w += hv*wv.w; }
                    if (nb > 2) { hv = s.hsb[2*DDIM + d];
                        a2.x += hv*wv.x; a2.y += hv*wv.y; a2.z += hv*wv.z; a2.w += hv*wv.w; }
                    if (nb > 3) { hv = s.hsb[3*DDIM + d];
                        a3.x += hv*wv.x; a3.y += hv*wv.y; a3.z += hv*wv.z; a3.w += hv*wv.w; }
                }
                *(float4*)(s.part + 0*4*HD + grp*HD + 4*q) = a0;
                if (nb > 1) *(float4*)(s.part + 1*4*HD + grp*HD + 4*q) = a1;
                if (nb > 2) *(float4*)(s.part + 2*4*HD + grp*HD + 4*q) = a2;
                if (nb > 3) *(float4*)(s.part + 3*4*HD + grp*HD + 4*q) = a3;
            }
            __syncthreads();
            for (int e = 0; e < nb; e++) {
                const float* pe = s.part + e*4*HD;
                s.xle[e*HD + t] = blv + pe[t] + pe[HD+t] + pe[2*HD+t] + pe[3*HD+t];
            }

            if (!got) {   // xr0 needed only from the leaky step onward
                if (t == 0) {
                    volatile int* xd = &g_xr0_done;
                    while (*xd < NPROD) {}
                }
                __syncthreads();
                __threadfence();
                myxr0 = g_xr0[t];
                got = true;
            }
            __syncthreads();

            for (int e = 0; e < nb; e++) {
                const float xlv = s.xle[e*HD + t];
                const float xs = xlv + myxr0;
                const float lr = xs >= 0.f ? xs : 0.2f * xs;   // leaky 0.2
                float v = lr * attv;
                #pragma unroll
                for (int off = 16; off; off >>= 1)
                    v += __shfl_xor_sync(0xffffffffu, v, off);
                if (lane == 0) s.red[warp] = v;
                __syncthreads();
                if (t < HEADS) {
                    // softmax shift dropped (shift-invariant; logits O(1))
                    float p = __expf(s.red[4*t] + s.red[4*t+1] + s.red[4*t+2] + s.red[4*t+3]);
                    s.psh[t] = p;
                    accD += p;
                }
                __syncthreads();
                accN += s.psh[t >> 7] * xlv;
                __syncthreads();
            }
        }
        atomicAdd(&g_num[t], accN);
        if (t < HEADS) atomicAdd(&g_den[t], accD);
    }

    __threadfence();
    __syncthreads();
    if (t == 0) atomicAdd(&g_done, 1);
}

extern "C" void kernel_launch(void* const* d_in, const int* in_sizes, int n_in,
                              void* d_out, int out_size) {
    const float* nf       = (const float*)d_in[0];
    const float* hidden   = (const float*)d_in[1];
    const float* W_enc    = (const float*)d_in[2];
    const float* b_enc    = (const float*)d_in[3];
    const float* W_l      = (const float*)d_in[4];
    const float* b_l      = (const float*)d_in[5];
    const float* W_r      = (const float*)d_in[6];
    const float* b_r      = (const float*)d_in[7];
    const float* att      = (const float*)d_in[8];
    const float* gat_bias = (const float*)d_in[9];
    const float* W_ih     = (const float*)d_in[10];
    const float* W_hh     = (const float*)d_in[11];
    const float* b_ih     = (const float*)d_in[12];
    const float* b_hh     = (const float*)d_in[13];
    const int*   ei       = (const int*)d_in[14];
    float* out = (float*)d_out;

    int E = in_sizes[14] / 2;

    fused_stgat<<<NBLK, NTHR, DYN_BYTES>>>(
        nf, hidden, W_enc, b_enc, W_l, b_l, W_r, b_r,
        att, gat_bias, W_ih, W_hh, b_ih, b_hh, ei, E, out);
}

// round 14
// speedup vs baseline: 1.1577x; 1.1188x over previous
#include <cuda_runtime.h>
#include <math.h>

#define F_IN   32
#define DDIM   128
#define HEADS  4
#define HD     512
#define RNN3   384
#define NPROD  4                   // bids 0..3: xr0 quarter producers
#define NFIN   8                   // bids 4..11: GRU slice finales
#define NSC    48                  // bids 12..59: scanners
#define NBLK   (NPROD + NFIN + NSC)
#define NTHR   512
#define LCAP   96
#define EB     4                   // edges per batch through one W_l pass

// Persistent globals (allocation-free rule). Last slice finale resets state.
__device__ float g_num[HD];
__device__ float g_den[HEADS];
__device__ int   g_done;           // scanners
__device__ int   g_xr0_done;       // producers
__device__ int   g_fin;            // slice finales
__device__ float g_xr0[HD];

struct SMemScan {
    float Wenc[F_IN * DDIM];   // 16 KB: W_enc staged during the scan
    float part[EB * 4 * HD];   // 32 KB K-split partials
    float xle[EB * HD];        //  8 KB
    float hsb[EB * DDIM];
    float nfb[EB * F_IN];
    float red[16];
    float psh[HEADS];
};
struct SMemFin {
    float Wih[48 * DDIM];      // 24 KB: my 48 W_ih rows, staged during scan
    float hid[DDIM];
    float gat[DDIM];
    float ghpart[384];
    float ghs[48];             // gh + b_hh (layout g*16+k)
    float bihs[48];            // b_ih kept separate (n-gate: i_n + r*h_n)
    float gis[48];
    int   reset_me;
};
#define DYN_BYTES 65536

__global__ void __launch_bounds__(NTHR, 1) fused_stgat(
    const float* __restrict__ nf,     const float* __restrict__ hidden,
    const float* __restrict__ W_enc,  const float* __restrict__ b_enc,
    const float* __restrict__ W_l,    const float* __restrict__ b_l,
    const float* __restrict__ W_r,    const float* __restrict__ b_r,
    const float* __restrict__ att,    const float* __restrict__ gat_bias,
    const float* __restrict__ W_ih,   const float* __restrict__ W_hh,
    const float* __restrict__ b_ih,   const float* __restrict__ b_hh,
    const int*   __restrict__ ei,     int E,
    float* __restrict__ out)
{
    extern __shared__ __align__(16) char dynraw[];
    __shared__ int ls[LCAP];
    __shared__ int lcnt;

    const int t = threadIdx.x, b = blockIdx.x;
    const int warp = t >> 5, lane = t & 31;
    const int grp = t >> 7, q = t & 127;
    const int n4 = E >> 2;

    if (b < NPROD) {
        // ======== xr0 quarter producer: dims [128b, 128b+128) ========
        SMemScan& s = *reinterpret_cast<SMemScan*>(dynraw);
        if (t < F_IN) s.nfb[t] = nf[t];
        __syncthreads();
        {
            float a = 0.f;
            #pragma unroll
            for (int k = 0; k < 8; k++)
                a += s.nfb[grp*8 + k] * W_enc[(grp*8 + k)*DDIM + q];
            s.part[grp*DDIM + q] = a;
        }
        __syncthreads();
        if (t < DDIM)
            s.hsb[t] = fmaxf(b_enc[t] + s.part[t] + s.part[DDIM+t] + s.part[2*DDIM+t] + s.part[3*DDIM+t], 0.f);
        __syncthreads();
        {
            float a = 0.f;
            const float* Wb = W_r + (size_t)(grp*32)*HD + b*DDIM + q;
            #pragma unroll
            for (int j = 0; j < 32; j++)
                a += s.hsb[grp*32 + j] * Wb[(size_t)j*HD];
            s.part[grp*DDIM + q] = a;
        }
        __syncthreads();
        if (t < DDIM)
            g_xr0[b*DDIM + t] = b_r[b*DDIM + t]
                + s.part[t] + s.part[DDIM+t] + s.part[2*DDIM+t] + s.part[3*DDIM+t];
        __threadfence();
        __syncthreads();
        if (t == 0) atomicAdd(&g_xr0_done, 1);
        return;
    }

    if (b < NPROD + NFIN) {
        // ======== Slice finale w: GRU rows {128g+16w+k}, out dims [16w,16w+16) ========
        const int w = b - NPROD;
        SMemFin& f = *reinterpret_cast<SMemFin*>(dynraw);

        if (t < DDIM) f.hid[t] = hidden[t];
        __syncthreads();

        // gh slice = hidden @ W_hh rows
        if (t < 384) {
            const int g = t / 128, rem = t % 128, k = rem >> 3, kg = rem & 7;
            const int R = 128*g + 16*w + k;
            const float* Wr = W_hh + (size_t)R * DDIM;
            float a = 0.f;
            #pragma unroll
            for (int c = kg*16; c < kg*16 + 16; c++) a += f.hid[c] * Wr[c];
            f.ghpart[t] = a;
        }
        // stage my 48 W_ih rows -> smem (1536 float4; 3 per thread)
        for (int i = t; i < 48*DDIM/4; i += NTHR) {
            const int row = i >> 5, f4 = i & 31;        // 32 float4 per row
            const int g = row >> 4, k = row & 15;
            ((float4*)f.Wih)[i] =
                ((const float4*)W_ih)[(size_t)(128*g + 16*w + k)*32 + f4];
        }
        __syncthreads();
        if (t < 48) {
            const int g = t / 16, k = t % 16;
            const int R = 128*g + 16*w + k;
            float a = b_hh[R];
            #pragma unroll
            for (int kg = 0; kg < 8; kg++) a += f.ghpart[g*128 + k*8 + kg];
            f.ghs[t] = a;
            f.bihs[t] = b_ih[R];
        }

        // ---- single rendezvous: wait for all scanners (hot poll) ----
        if (t == 0) {
            volatile int* dn = &g_done;
            while (*dn < NSC) {}
        }
        __syncthreads();
        __threadfence();

        if (t < DDIM) {
            float s = 0.f;
            #pragma unroll
            for (int h = 0; h < HEADS; h++)
                s += g_num[h*DDIM + t] / fmaxf(g_den[h], 1e-16f);
            f.gat[t] = 0.25f * s + gat_bias[t];
        }
        __syncthreads();

        // gi: warp per row (lane = one float4 of the row), 3 rows per warp
        {
            const float4 gv = ((const float4*)f.gat)[lane];
            #pragma unroll
            for (int rr = 0; rr < 3; rr++) {
                const int row = warp*3 + rr;
                const float4 wv = ((const float4*)f.Wih)[row*32 + lane];
                float a = wv.x*gv.x + wv.y*gv.y + wv.z*gv.z + wv.w*gv.w;
                #pragma unroll
                for (int off = 16; off; off >>= 1)
                    a += __shfl_xor_sync(0xffffffffu, a, off);
                if (lane == 0) f.gis[row] = a + f.bihs[row];
            }
        }
        __syncthreads();

        if (t < 16) {
            const float r  = 1.f / (1.f + __expf(-(f.gis[t]      + f.ghs[t])));
            const float z  = 1.f / (1.f + __expf(-(f.gis[16 + t] + f.ghs[16 + t])));
            const float nx = f.gis[32 + t] + r * f.ghs[32 + t];
            const float e2 = __expf(-2.f * nx);
            const float ng = (1.f - e2) / (1.f + e2);   // tanh
            out[16*w + t] = (1.f - z) * ng + z * f.hid[16*w + t];
        }
        __threadfence();
        __syncthreads();

        // last-arriving finale resets persistent state for the next replay
        if (t == 0) f.reset_me = (atomicAdd(&g_fin, 1) == NFIN - 1);
        __syncthreads();
        if (f.reset_me) {
            g_num[t] = 0.f;
            if (t < HEADS) g_den[t] = 0.f;
            if (t == 0) { g_done = 0; g_xr0_done = 0; g_fin = 0; }
        }
        return;
    }

    // ================= Scanner blocks (bids 12..59) =================
    SMemScan& s = *reinterpret_cast<SMemScan*>(dynraw);
    if (t == 0) lcnt = 0;
    __syncthreads();

    // preload W_enc to smem + bias/att regs, overlapped with the scan loads
    ((float4*)s.Wenc)[t]       = ((const float4*)W_enc)[t];
    ((float4*)s.Wenc)[t + 512] = ((const float4*)W_enc)[t + 512];
    const float attv = att[t];   // att [4,128] row-major == att[t]
    const float blv  = b_l[t];

    const int idx = b - NPROD - NFIN;
    const int chunk = (n4 + NSC - 1) / NSC;
    const int lo = idx * chunk;
    const int hi = min(n4, lo + chunk);
    const int4* dst4 = (const int4*)(ei + E);
    if (idx == 0) {
        if (t == 0) ls[atomicAdd(&lcnt, 1)] = 0;    // self-loop of node 0
        for (int i = 4*n4 + t; i < E; i += NTHR)    // tail if E % 4
            if (ei[E + i] == 0) ls[atomicAdd(&lcnt, 1)] = ei[i];
    }
    // unroll-4 batched scan: all loads in flight before any test
    for (int i = lo + t; i < hi; i += 4*NTHR) {
        int4 va[4];
        #pragma unroll
        for (int u = 0; u < 4; u++) {
            const int ii = i + u*NTHR;
            va[u] = (ii < hi) ? dst4[ii] : make_int4(1, 1, 1, 1);
        }
        #pragma unroll
        for (int u = 0; u < 4; u++) {
            const int ii = i + u*NTHR;
            if (va[u].x == 0) ls[atomicAdd(&lcnt, 1)] = ei[4*ii+0];
            if (va[u].y == 0) ls[atomicAdd(&lcnt, 1)] = ei[4*ii+1];
            if (va[u].z == 0) ls[atomicAdd(&lcnt, 1)] = ei[4*ii+2];
            if (va[u].w == 0) ls[atomicAdd(&lcnt, 1)] = ei[4*ii+3];
        }
    }
    __syncthreads();

    const int cnt = min(lcnt, LCAP);
    if (cnt > 0) {
        bool got = false;
        float myxr0 = 0.f;
        float accN = 0.f;
        float accD = 0.f;

        for (int base = 0; base < cnt; base += EB) {
            const int nb = min(EB, cnt - base);

            if (t < nb * F_IN) {   // stage nf rows
                const int e = t >> 5, k = t & 31;
                s.nfb[e*F_IN + k] = nf[(size_t)ls[base + e]*F_IN + k];
            }
            __syncthreads();
            if (grp < nb) {        // hs for up to 4 edges in parallel (smem W_enc)
                float a = b_enc[q];
                #pragma unroll
                for (int k = 0; k < F_IN; k++)
                    a += s.nfb[grp*F_IN + k] * s.Wenc[k*DDIM + q];
                s.hsb[grp*DDIM + q] = fmaxf(a, 0.f);
            }
            __syncthreads();
            {   // xl for all batch edges through ONE W_l pass (float4 K-split)
                float4 a0 = make_float4(0.f,0.f,0.f,0.f);
                float4 a1 = a0, a2 = a0, a3 = a0;
                const float* Wb = W_l + (size_t)(grp*32)*HD + 4*q;
                #pragma unroll
                for (int j = 0; j < 32; j++) {
                    const float4 wv = *(const float4*)(Wb + (size_t)j*HD);
                    const int d = grp*32 + j;
                    float hv;
                    hv = s.hsb[0*DDIM + d];
                    a0.x += hv*wv.x; a0.y += hv*wv.y; a0.z += hv*wv.z; a0.w += hv*wv.w;
                    if (nb > 1) { hv = s.hsb[1*DDIM + d];
                        a1.x += hv*wv.x; a1.y += hv*wv.y; a1.z += hv*wv.z; a1.w += hv*wv.w; }
                    if (nb > 2) { hv = s.hsb[2*DDIM + d];
                        a2.x += hv*wv.x; a2.y += hv*wv.y; a2.z += hv*wv.z; a2.w += hv*wv.w; }
                    if (nb > 3) { hv = s.hsb[3*DDIM + d];
                        a3.x += hv*wv.x; a3.y += hv*wv.y; a3.z += hv*wv.z; a3.w += hv*wv.w; }
                }
                *(float4*)(s.part + 0*4*HD + grp*HD + 4*q) = a0;
                if (nb > 1) *(float4*)(s.part + 1*4*HD + grp*HD + 4*q) = a1;
                if (nb > 2) *(float4*)(s.part + 2*4*HD + grp*HD + 4*q) = a2;
                if (nb > 3) *(float4*)(s.part + 3*4*HD + grp*HD + 4*q) = a3;
            }
            __syncthreads();
            for (int e = 0; e < nb; e++) {
                const float* pe = s.part + e*4*HD;
                s.xle[e*HD + t] = blv + pe[t] + pe[HD+t] + pe[2*HD+t] + pe[3*HD+t];
            }

            if (!got) {   // xr0 needed only from the leaky step onward
                if (t == 0) {
                    volatile int* xd = &g_xr0_done;
                    while (*xd < NPROD) {}
                }
                __syncthreads();
                __threadfence();
                myxr0 = g_xr0[t];
                got = true;
            }
            __syncthreads();

            for (int e = 0; e < nb; e++) {
                const float xlv = s.xle[e*HD + t];
                const float xs = xlv + myxr0;
                const float lr = xs >= 0.f ? xs : 0.2f * xs;   // leaky 0.2
                float v = lr * attv;
                #pragma unroll
                for (int off = 16; off; off >>= 1)
                    v += __shfl_xor_sync(0xffffffffu, v, off);
                if (lane == 0) s.red[warp] = v;
                __syncthreads();
                if (t < HEADS) {
                    // softmax shift dropped (shift-invariant; logits O(1))
                    float p = __expf(s.red[4*t] + s.red[4*t+1] + s.red[4*t+2] + s.red[4*t+3]);
                    s.psh[t] = p;
                    accD += p;
                }
                __syncthreads();
                accN += s.psh[t >> 7] * xlv;
                __syncthreads();
            }
        }
        atomicAdd(&g_num[t], accN);
        if (t < HEADS) atomicAdd(&g_den[t], accD);
    }

    __threadfence();
    __syncthreads();
    if (t == 0) atomicAdd(&g_done, 1);
}

extern "C" void kernel_launch(void* const* d_in, const int* in_sizes, int n_in,
                              void* d_out, int out_size) {
    const float* nf       = (const float*)d_in[0];
    const float* hidden   = (const float*)d_in[1];
    const float* W_enc    = (const float*)d_in[2];
    const float* b_enc    = (const float*)d_in[3];
    const float* W_l      = (const float*)d_in[4];
    const float* b_l      = (const float*)d_in[5];
    const float* W_r      = (const float*)d_in[6];
    const float* b_r      = (const float*)d_in[7];
    const float* att      = (const float*)d_in[8];
    const float* gat_bias = (const float*)d_in[9];
    const float* W_ih     = (const float*)d_in[10];
    const float* W_hh     = (const float*)d_in[11];
    const float* b_ih     = (const float*)d_in[12];
    const float* b_hh     = (const float*)d_in[13];
    const int*   ei       = (const int*)d_in[14];
    float* out = (float*)d_out;

    int E = in_sizes[14] / 2;

    static int attr_set = 0;
    if (!attr_set) {
        cudaFuncSetAttribute(fused_stgat, cudaFuncAttributeMaxDynamicSharedMemorySize,
                             DYN_BYTES);
        attr_set = 1;
    }
    fused_stgat<<<NBLK, NTHR, DYN_BYTES>>>(
        nf, hidden, W_enc, b_enc, W_l, b_l, W_r, b_r,
        att, gat_bias, W_ih, W_hh, b_ih, b_hh, ei, E, out);
}